// round 8
// baseline (speedup 1.0000x reference)
#include <cuda_runtime.h>

// PolynomialFlowRegularizer: B=64, C=2, H=512, W=512
// err_{b,c} = ( ||f||^2 - rhs^T G^{-1} rhs ) / N  ; out = sum_{b,c} err / B
// Single fused kernel: streaming partials + last-block closed-form finalize.
// Streaming config = R1's measured-5.9TB/s shape: CHUNKS=16, natural regalloc.

#define Wd 512
#define Hd 512
#define NCH 128                    // B*C = 64*2
#define NPIX (Hd * Wd)             // 262144
#define CHUNKS 16                  // blocks per channel
#define TPB 256
#define VECS_PER_CH (NPIX / 4)     // 65536 float4
#define VECS_PER_CHUNK (VECS_PER_CH / CHUNKS)   // 4096
#define VECS_PER_THREAD (VECS_PER_CHUNK / TPB)  // 16
#define TOTAL_BLOCKS (CHUNKS * NCH)             // 2048

// per-block partials: [channel][chunk][7] ; 7 = {s2, r0..r5}
__device__ float g_part[NCH * CHUNKS * 7];
__device__ unsigned int g_count = 0;

// ---- compile-time closed-form G^{-1} pieces (grid symmetric, odd moments = 0) ----
// x_i = -1 + 2i/511, i = 0..511
constexpr double S0  = 512.0;
constexpr double hh  = 2.0 / 511.0;
constexpr double Si1 = 130816.0;                                  // sum i
constexpr double Si2 = 44608256.0;                                // sum i^2
constexpr double Si3 = 17112825856.0;                             // sum i^3 = (sum i)^2
constexpr double Si4 = 511.0 * 512.0 * 1023.0 * 784895.0 / 30.0;  // sum i^4
constexpr double S2v = S0 - 2.0 * hh * Si1 + hh * hh * Si2;
constexpr double S4v = S0 - 4.0 * hh * Si1 + 6.0 * hh * hh * Si2
                      - 4.0 * hh * hh * hh * Si3 + hh * hh * hh * hh * Si4;
// 3x3 block over {1, x^2, y^2}: [[a,b,b],[b,c,d],[b,d,c]]
constexpr double Ga = S0 * S0, Gb = S0 * S2v, Gc = S0 * S4v, Gd = S2v * S2v;
constexpr double Gdet = (Gc - Gd) * (Ga * (Gc + Gd) - 2.0 * Gb * Gb);
constexpr double i00  = (Gc * Gc - Gd * Gd) / Gdet;
constexpr double i01  = -Gb * (Gc - Gd) / Gdet;   // == i02 by symmetry
constexpr double i11  = (Ga * Gc - Gb * Gb) / Gdet;
constexpr double i12  = -(Ga * Gd - Gb * Gb) / Gdet;
constexpr double invXX  = 1.0 / (S0 * S2v);       // x, y diagonals
constexpr double invXY  = 1.0 / (S2v * S2v);      // xy diagonal
constexpr double OUTSCL = 1.0 / ((double)NPIX * 64.0);  // /N per channel, /B at end

__global__ __launch_bounds__(TPB) void pfr_fused(const float4* __restrict__ in,
                                                 float* __restrict__ out) {
    const int chunk = blockIdx.x;   // 0..CHUNKS-1
    const int bc    = blockIdx.y;   // 0..NCH-1
    const int t     = threadIdx.x;

    const float4* base = in + (size_t)bc * VECS_PER_CH + (size_t)chunk * VECS_PER_CHUNK;
    const float sc = 2.0f / 511.0f;

    float s2 = 0.f, r0 = 0.f, r1 = 0.f, r2 = 0.f, r3 = 0.f, r4 = 0.f, r5 = 0.f;

#pragma unroll
    for (int k = 0; k < VECS_PER_THREAD; k++) {
        const int v  = k * TPB + t;                // local vec index in chunk
        const int vg = chunk * VECS_PER_CHUNK + v; // global vec index in channel
        float4 f = __ldcs(&base[v]);               // streaming: read-once, evict-first

        const float yf  = fmaf((float)(vg >> 7), sc, -1.0f);        // row (128 vecs/row)
        const float xf0 = fmaf((float)((vg & 127) << 2), sc, -1.0f);
        const float xf1 = xf0 + sc;
        const float xf2 = xf1 + sc;
        const float xf3 = xf2 + sc;

        const float sf = (f.x + f.y) + (f.z + f.w);
        float sfx  = f.x * xf0;
        sfx = fmaf(f.y, xf1, sfx);
        sfx = fmaf(f.z, xf2, sfx);
        sfx = fmaf(f.w, xf3, sfx);
        float sfx2 = f.x * xf0 * xf0;
        sfx2 = fmaf(f.y * xf1, xf1, sfx2);
        sfx2 = fmaf(f.z * xf2, xf2, sfx2);
        sfx2 = fmaf(f.w * xf3, xf3, sfx2);

        s2 = fmaf(f.x, f.x, s2);
        s2 = fmaf(f.y, f.y, s2);
        s2 = fmaf(f.z, f.z, s2);
        s2 = fmaf(f.w, f.w, s2);

        r0 += sf;
        r1 += sfx;
        r2 = fmaf(sf, yf, r2);
        r3 += sfx2;
        r4 = fmaf(sfx, yf, r4);
        r5 = fmaf(sf * yf, yf, r5);
    }

    // ---- block-local deterministic reduction ----
    float vals[7] = {s2, r0, r1, r2, r3, r4, r5};
#pragma unroll
    for (int i = 0; i < 7; i++) {
#pragma unroll
        for (int off = 16; off > 0; off >>= 1)
            vals[i] += __shfl_down_sync(0xFFFFFFFFu, vals[i], off);
    }

    __shared__ float sh[8][7];  // 8 warps
    const int warp = t >> 5;
    const int lane = t & 31;
    if (lane == 0) {
#pragma unroll
        for (int i = 0; i < 7; i++) sh[warp][i] = vals[i];
    }
    __syncthreads();

    if (t == 0) {
        float* dst = &g_part[((size_t)bc * CHUNKS + chunk) * 7];
#pragma unroll
        for (int i = 0; i < 7; i++) {
            float s = sh[0][i];
#pragma unroll
            for (int w = 1; w < 8; w++) s += sh[w][i];
            dst[i] = s;
        }
    }

    // ---- last-block finalize (threadfence-reduction pattern) ----
    __shared__ bool amLast;
    __threadfence();                 // make this block's partials visible
    if (t == 0)
        amLast = (atomicAdd(&g_count, 1u) == TOTAL_BLOCKS - 1);
    __syncthreads();
    if (!amLast) return;

    if (t == 0) g_count = 0;         // reset for next graph replay
    __threadfence();

    // one thread per channel: fold 16 chunk-partials in double
    double err = 0.0;
    if (t < NCH) {
        double s[7] = {0, 0, 0, 0, 0, 0, 0};
#pragma unroll
        for (int cc = 0; cc < CHUNKS; cc++) {
            const float* p = &g_part[((size_t)t * CHUNKS + cc) * 7];
#pragma unroll
            for (int i = 0; i < 7; i++) s[i] += (double)__ldcg(&p[i]);
        }
        // s[0]=||f||^2 ; rhs over [1, x, y, x^2, xy, y^2]
        const double m0 = s[1], mx = s[2], my = s[3], mxx = s[4], mxy = s[5], myy = s[6];
        double quad = (mx * mx + my * my) * invXX + mxy * mxy * invXY;
        quad += i00 * m0 * m0 + 2.0 * i01 * m0 * (mxx + myy)
              + i11 * (mxx * mxx + myy * myy) + 2.0 * i12 * mxx * myy;
        err = s[0] - quad;
    }

    // deterministic tree reduction across 128 channels (first 4 warps carry data)
#pragma unroll
    for (int off = 16; off > 0; off >>= 1)
        err += __shfl_down_sync(0xFFFFFFFFu, err, off);

    __shared__ double wsum[4];
    if (lane == 0 && warp < 4) wsum[warp] = err;
    __syncthreads();

    if (t == 0) {
        double total = wsum[0] + wsum[1] + wsum[2] + wsum[3];
        out[0] = (float)(total * OUTSCL);
    }
}

extern "C" void kernel_launch(void* const* d_in, const int* in_sizes, int n_in,
                              void* d_out, int out_size) {
    (void)in_sizes; (void)n_in; (void)out_size;
    const float4* in = (const float4*)d_in[0];
    float* out = (float*)d_out;
    pfr_fused<<<dim3(CHUNKS, NCH), TPB>>>(in, out);
}

// round 9
// speedup vs baseline: 1.3980x; 1.3980x over previous
#include <cuda_runtime.h>

// PolynomialFlowRegularizer: B=64, C=2, H=512, W=512
// err_{b,c} = ( ||f||^2 - rhs^T G^{-1} rhs ) / N  ; out = sum_{b,c} err / B
// Fused kernel: explicit 4-wide MLP streaming + last-block closed-form finalize.
// Grid = 512 blocks (CHUNKS=4): single wave at >=6 blocks/SM, zero tail.

#define Wd 512
#define Hd 512
#define NCH 128                    // B*C = 64*2
#define NPIX (Hd * Wd)             // 262144
#define CHUNKS 4                   // blocks per channel
#define TPB 256
#define VECS_PER_CH (NPIX / 4)     // 65536 float4
#define VECS_PER_CHUNK (VECS_PER_CH / CHUNKS)   // 16384
#define BATCHES (VECS_PER_CHUNK / (4 * TPB))    // 16 batches of 4 vecs/thread
#define TOTAL_BLOCKS (CHUNKS * NCH)             // 512

// per-block partials: [channel][chunk][7] ; 7 = {s2, r0..r5}
__device__ float g_part[NCH * CHUNKS * 7];
__device__ unsigned int g_count = 0;

// ---- compile-time closed-form G^{-1} pieces (grid symmetric, odd moments = 0) ----
constexpr double S0  = 512.0;
constexpr double hh  = 2.0 / 511.0;
constexpr double Si1 = 130816.0;
constexpr double Si2 = 44608256.0;
constexpr double Si3 = 17112825856.0;
constexpr double Si4 = 511.0 * 512.0 * 1023.0 * 784895.0 / 30.0;
constexpr double S2v = S0 - 2.0 * hh * Si1 + hh * hh * Si2;
constexpr double S4v = S0 - 4.0 * hh * Si1 + 6.0 * hh * hh * Si2
                      - 4.0 * hh * hh * hh * Si3 + hh * hh * hh * hh * Si4;
constexpr double Ga = S0 * S0, Gb = S0 * S2v, Gc = S0 * S4v, Gd = S2v * S2v;
constexpr double Gdet = (Gc - Gd) * (Ga * (Gc + Gd) - 2.0 * Gb * Gb);
constexpr double i00  = (Gc * Gc - Gd * Gd) / Gdet;
constexpr double i01  = -Gb * (Gc - Gd) / Gdet;
constexpr double i11  = (Ga * Gc - Gb * Gb) / Gdet;
constexpr double i12  = -(Ga * Gd - Gb * Gb) / Gdet;
constexpr double invXX  = 1.0 / (S0 * S2v);
constexpr double invXY  = 1.0 / (S2v * S2v);
constexpr double OUTSCL = 1.0 / ((double)NPIX * 64.0);

struct Acc { float s2, r0, r1, r2, r3, r4, r5; };

__device__ __forceinline__ void accum(Acc& a, float4 f, int vg) {
    const float sc = 2.0f / 511.0f;
    const float yf  = fmaf((float)(vg >> 7), sc, -1.0f);        // row (128 vecs/row)
    const float xf0 = fmaf((float)((vg & 127) << 2), sc, -1.0f);
    const float xf1 = xf0 + sc;
    const float xf2 = xf1 + sc;
    const float xf3 = xf2 + sc;

    const float sf = (f.x + f.y) + (f.z + f.w);
    float sfx  = f.x * xf0;
    sfx = fmaf(f.y, xf1, sfx);
    sfx = fmaf(f.z, xf2, sfx);
    sfx = fmaf(f.w, xf3, sfx);
    float sfx2 = f.x * xf0 * xf0;
    sfx2 = fmaf(f.y * xf1, xf1, sfx2);
    sfx2 = fmaf(f.z * xf2, xf2, sfx2);
    sfx2 = fmaf(f.w * xf3, xf3, sfx2);

    a.s2 = fmaf(f.x, f.x, a.s2);
    a.s2 = fmaf(f.y, f.y, a.s2);
    a.s2 = fmaf(f.z, f.z, a.s2);
    a.s2 = fmaf(f.w, f.w, a.s2);

    a.r0 += sf;
    a.r1 += sfx;
    a.r2 = fmaf(sf, yf, a.r2);
    a.r3 += sfx2;
    a.r4 = fmaf(sfx, yf, a.r4);
    a.r5 = fmaf(sf * yf, yf, a.r5);
}

__global__ __launch_bounds__(TPB) void pfr_fused(const float4* __restrict__ in,
                                                 float* __restrict__ out) {
    const int chunk = blockIdx.x;   // 0..CHUNKS-1
    const int bc    = blockIdx.y;   // 0..NCH-1
    const int t     = threadIdx.x;

    const float4* base = in + (size_t)bc * VECS_PER_CH + (size_t)chunk * VECS_PER_CHUNK;
    Acc a = {0.f, 0.f, 0.f, 0.f, 0.f, 0.f, 0.f};

#pragma unroll 4
    for (int k = 0; k < BATCHES; k++) {
        const int v0 = k * (4 * TPB) + t;        // 4 loads, stride TPB apart
        // front-batched loads: explicit MLP=4
        float4 f0 = __ldcs(&base[v0 + 0 * TPB]);
        float4 f1 = __ldcs(&base[v0 + 1 * TPB]);
        float4 f2 = __ldcs(&base[v0 + 2 * TPB]);
        float4 f3 = __ldcs(&base[v0 + 3 * TPB]);

        const int vg0 = chunk * VECS_PER_CHUNK + v0;
        accum(a, f0, vg0 + 0 * TPB);
        accum(a, f1, vg0 + 1 * TPB);
        accum(a, f2, vg0 + 2 * TPB);
        accum(a, f3, vg0 + 3 * TPB);
    }

    // ---- block-local deterministic reduction ----
    float vals[7] = {a.s2, a.r0, a.r1, a.r2, a.r3, a.r4, a.r5};
#pragma unroll
    for (int i = 0; i < 7; i++) {
#pragma unroll
        for (int off = 16; off > 0; off >>= 1)
            vals[i] += __shfl_down_sync(0xFFFFFFFFu, vals[i], off);
    }

    __shared__ float sh[8][7];  // 8 warps
    const int warp = t >> 5;
    const int lane = t & 31;
    if (lane == 0) {
#pragma unroll
        for (int i = 0; i < 7; i++) sh[warp][i] = vals[i];
    }
    __syncthreads();

    if (t == 0) {
        float* dst = &g_part[((size_t)bc * CHUNKS + chunk) * 7];
#pragma unroll
        for (int i = 0; i < 7; i++) {
            float s = sh[0][i];
#pragma unroll
            for (int w = 1; w < 8; w++) s += sh[w][i];
            dst[i] = s;
        }
    }

    // ---- last-block finalize (threadfence-reduction pattern) ----
    __shared__ bool amLast;
    __threadfence();
    if (t == 0)
        amLast = (atomicAdd(&g_count, 1u) == TOTAL_BLOCKS - 1);
    __syncthreads();
    if (!amLast) return;

    if (t == 0) g_count = 0;         // reset for next graph replay
    __threadfence();

    // one thread per channel: fold 4 chunk-partials in double
    double err = 0.0;
    if (t < NCH) {
        double s[7] = {0, 0, 0, 0, 0, 0, 0};
#pragma unroll
        for (int cc = 0; cc < CHUNKS; cc++) {
            const float* p = &g_part[((size_t)t * CHUNKS + cc) * 7];
#pragma unroll
            for (int i = 0; i < 7; i++) s[i] += (double)__ldcg(&p[i]);
        }
        const double m0 = s[1], mx = s[2], my = s[3], mxx = s[4], mxy = s[5], myy = s[6];
        double quad = (mx * mx + my * my) * invXX + mxy * mxy * invXY;
        quad += i00 * m0 * m0 + 2.0 * i01 * m0 * (mxx + myy)
              + i11 * (mxx * mxx + myy * myy) + 2.0 * i12 * mxx * myy;
        err = s[0] - quad;
    }

    // deterministic tree reduction across 128 channels
#pragma unroll
    for (int off = 16; off > 0; off >>= 1)
        err += __shfl_down_sync(0xFFFFFFFFu, err, off);

    __shared__ double wsum[4];
    if (lane == 0 && warp < 4) wsum[warp] = err;
    __syncthreads();

    if (t == 0) {
        double total = wsum[0] + wsum[1] + wsum[2] + wsum[3];
        out[0] = (float)(total * OUTSCL);
    }
}

extern "C" void kernel_launch(void* const* d_in, const int* in_sizes, int n_in,
                              void* d_out, int out_size) {
    (void)in_sizes; (void)n_in; (void)out_size;
    const float4* in = (const float4*)d_in[0];
    float* out = (float*)d_out;
    pfr_fused<<<dim3(CHUNKS, NCH), TPB>>>(in, out);
}